// round 15
// baseline (speedup 1.0000x reference)
#include <cuda_runtime.h>
#include <cuda_bf16.h>
#include <math.h>
#include <stdint.h>

#define BATCH 256
#define SEQ   256
#define EMB   1024
#define HID   1024
#define NCLS  32000
#define G4    4096          // 4 gates * HID
#define WROW  2048          // EMB + HID
#define HB    (BATCH*HID)   // 262144
#define HB2   (2*BATCH*HID) // 524288 (2 dirs)
#define KS    32            // K chunk
#define NCH   32            // 1024 / 32 chunks

// HMMA kernel smem layout (128x128 tile, 4-stage pipeline)
#define NSTG  4
#define STGB  8192          // 128 rows x 32 bf16 per stage
#define SMB_B 32768
#define SM_TOKS 67584
#define SMEMSZ  69632

// persistent step kernel smem layout
#define PW       68                      // pre row stride (floats)
#define SMP_B    0                       // 32 x 4096 = 131072 (Wh resident)
#define SMP_A    131072                  // 3 x 16384 A buffers
#define SMP_PRE  (131072 + 49152)        // 128*68*4 = 34816
#define SMP_BIAS (131072 + 49152 + 34816)
#define SMEMP    (131072 + 49152 + 34816 + 256)   // 215296

// Scratch (device globals: allocation-free rule)
static __device__ __nv_bfloat16  g_XWb[(size_t)2 * SEQ * BATCH * G4]; // raw x-preacts (no bias)
static __device__ __nv_bfloat16  g_Cb[(size_t)NCLS * EMB];
static __device__ __nv_bfloat16  g_Whb[(size_t)2 * G4 * HID];   // [d][col*4+gi][k]
static __device__ __nv_bfloat16  g_Wxb[(size_t)2 * G4 * EMB];   // [d][col*4+gi][k]
static __device__ __nv_bfloat16  g_hb[2 * HB2];                 // [pingpong][dir][b][col]
static __device__ float          g_hsum[HB];                    // fp32 h1+h2
static __device__ float          g_biasI[2 * G4];
static __device__ unsigned       g_bar2[2];                      // per-direction barriers

// ---------------------------------------------------------------------------
__device__ __forceinline__ uint32_t smem_u32(const void* p) {
    uint32_t a;
    asm("{ .reg .u64 t; cvta.to.shared.u64 t, %1; cvt.u32.u64 %0, t; }" : "=r"(a) : "l"(p));
    return a;
}
__device__ __forceinline__ void cp16(uint32_t s, const void* g) {
    asm volatile("cp.async.ca.shared.global [%0], [%1], 16;"
                 :: "r"(s), "l"(__cvta_generic_to_global(g)) : "memory");
}
__device__ __forceinline__ void cp16cg(uint32_t s, const void* g) {   // L1-bypass
    asm volatile("cp.async.cg.shared.global [%0], [%1], 16;"
                 :: "r"(s), "l"(__cvta_generic_to_global(g)) : "memory");
}
#define CP_COMMIT() asm volatile("cp.async.commit_group;" ::: "memory")
#define CP_WAIT(n)  asm volatile("cp.async.wait_group %0;" :: "n"(n) : "memory")

#define LDSM4(R, A) \
    asm volatile("ldmatrix.sync.aligned.m8n8.x4.shared.b16 {%0,%1,%2,%3}, [%4];" \
        : "=r"((R)[0]), "=r"((R)[1]), "=r"((R)[2]), "=r"((R)[3]) : "r"(A))

__device__ __forceinline__ void mma_bf16(float* d, const uint32_t* a, const uint32_t* b)
{
    asm volatile(
        "mma.sync.aligned.m16n8k16.row.col.f32.bf16.bf16.f32 "
        "{%0,%1,%2,%3}, {%4,%5,%6,%7}, {%8,%9}, {%0,%1,%2,%3};\n"
        : "+f"(d[0]), "+f"(d[1]), "+f"(d[2]), "+f"(d[3])
        : "r"(a[0]), "r"(a[1]), "r"(a[2]), "r"(a[3]), "r"(b[0]), "r"(b[1]));
}

// 16B-slot swizzle: row r, 16B-chunk c (0..3 over 32 bf16 k). Conflict-free.
__device__ __forceinline__ uint32_t slotb(int r, int c) {
    return (uint32_t)((r << 6) + ((c ^ ((r >> 1) & 3)) << 4));
}

// ---------------------------------------------------------------------------
__global__ void init_kernel()
{
    int i = blockIdx.x * blockDim.x + threadIdx.x;
    if (i < 2) g_bar2[i] = 0u;
    if (i < HB2) reinterpret_cast<uint32_t*>(g_hb)[i] = 0u;
}

__global__ __launch_bounds__(256) void convw_kernel(
    const float* __restrict__ W0, const float* __restrict__ W1,
    const float* __restrict__ W2, const float* __restrict__ W3,
    const float* __restrict__ W4, const float* __restrict__ W5,
    const float* __restrict__ W6, const float* __restrict__ W7)
{
    const float* Ws[8] = {W0,W1,W2,W3,W4,W5,W6,W7};
    int r = blockIdx.x;             // 0..16383
    int k = threadIdx.x * 4;
    const float* src;
    __nv_bfloat16* dst;
    if (r < 8192) {
        int d = r >> 12, np = r & 4095, gi = np & 3, col = np >> 2;
        src = Ws[d*4 + gi] + (size_t)col * WROW + EMB + k;
        dst = g_Whb + (size_t)r * HID + k;
    } else {
        int rr = r - 8192;
        int d = rr >> 12, np = rr & 4095, gi = np & 3, col = np >> 2;
        src = Ws[d*4 + gi] + (size_t)col * WROW + k;
        dst = g_Wxb + (size_t)rr * EMB + k;
    }
    float4 v = *(const float4*)src;
    __nv_bfloat162 lo; lo.x = __float2bfloat16(v.x); lo.y = __float2bfloat16(v.y);
    __nv_bfloat162 hi; hi.x = __float2bfloat16(v.z); hi.y = __float2bfloat16(v.w);
    *reinterpret_cast<__nv_bfloat162*>(dst)     = lo;
    *reinterpret_cast<__nv_bfloat162*>(dst + 2) = hi;
}

__global__ __launch_bounds__(256) void convc_kernel(const float* __restrict__ C)
{
    size_t row = blockIdx.x;
    int k = threadIdx.x * 4;
    float4 v = *(const float4*)(C + row * EMB + k);
    __nv_bfloat16* dst = g_Cb + row * EMB + k;
    __nv_bfloat162 lo; lo.x = __float2bfloat16(v.x); lo.y = __float2bfloat16(v.y);
    __nv_bfloat162 hi; hi.x = __float2bfloat16(v.z); hi.y = __float2bfloat16(v.w);
    *reinterpret_cast<__nv_bfloat162*>(dst)     = lo;
    *reinterpret_cast<__nv_bfloat162*>(dst + 2) = hi;
}

__global__ void bias_kernel(
    const float* __restrict__ B0, const float* __restrict__ B1,
    const float* __restrict__ B2, const float* __restrict__ B3,
    const float* __restrict__ B4, const float* __restrict__ B5,
    const float* __restrict__ B6, const float* __restrict__ B7)
{
    const float* Bs[8] = {B0,B1,B2,B3,B4,B5,B6,B7};
    int n = blockIdx.x * blockDim.x + threadIdx.x;
    if (n < 2 * G4) {
        int d = n >> 12, rr = n & 4095, gi = rr & 3, col = rr >> 2;
        g_biasI[n] = Bs[d*4 + gi][col];
    }
}

// ---------------------------------------------------------------------------
// xproj: XWb = gathered C[X] @ Wx^T (raw preacts, bf16 out, NO bias).
// 128x128 tile, 8 warps (2m x 4n), KS=32, 4-stage cp.async, ldmatrix.
// __launch_bounds__(256, 2): cap regs at 128 so TWO CTAs co-reside per SM
// (2 x 68KB smem = 136KB < 228KB) -> covers sync/LDSM stalls, lifts tensor%.
// ---------------------------------------------------------------------------
__global__ __launch_bounds__(256, 2) void xproj_hm(const int* __restrict__ X)
{
    extern __shared__ __align__(16) char sm[];
    const uint32_t smb = smem_u32(sm);
    const int tid = threadIdx.x;
    const int lane = tid & 31, warp = tid >> 5;
    const int nbase = blockIdx.x * 128;
    const int mbase = blockIdx.y * 128;
    const int m0 = (warp >> 2) * 64, n0 = (warp & 3) * 32;

    if (tid < 128) {
        int m = mbase + tid;
        ((int*)(sm + SM_TOKS))[tid] = X[(m & 255) * SEQ + (m >> 8)];   // X[b][t]
    }
    __syncthreads();

    const __nv_bfloat16* aRow = g_Cb + (size_t)((int*)(sm + SM_TOKS))[tid >> 1] * EMB;
    const __nv_bfloat16* bRow = g_Wxb + (size_t)(nbase + (tid >> 1)) * EMB;

    float acc[16][4];
#pragma unroll
    for (int i = 0; i < 16; ++i)
#pragma unroll
        for (int j = 0; j < 4; ++j) acc[i][j] = 0.f;

    {
        const int rL = tid >> 1, cL = (tid & 1) * 2;
        const uint32_t sa0 = smb + slotb(rL, cL);
        const uint32_t sa1 = smb + slotb(rL, cL + 1);
        const uint32_t sb0 = smb + SMB_B + slotb(rL, cL);
        const uint32_t sb1 = smb + SMB_B + slotb(rL, cL + 1);
        const __nv_bfloat16* gA = aRow + cL * 8;
        const __nv_bfloat16* gB = bRow + cL * 8;

        uint32_t aAddr[4], bAddr[2];
#pragma unroll
        for (int mi = 0; mi < 4; ++mi)
            aAddr[mi] = smb + slotb(m0 + mi * 16 + (lane & 15), lane >> 4);
#pragma unroll
        for (int p = 0; p < 2; ++p)
            bAddr[p] = smb + SMB_B
                     + slotb(n0 + (2 * p + ((lane >> 4) & 1)) * 8 + (lane & 7), (lane >> 3) & 1);

#pragma unroll
        for (int st = 0; st < NSTG - 1; ++st) {
            const int kb = st * KS;
            cp16(sa0 + st * STGB, gA + kb);
            cp16(sa1 + st * STGB, gA + kb + 8);
            cp16(sb0 + st * STGB, gB + kb);
            cp16(sb1 + st * STGB, gB + kb + 8);
            CP_COMMIT();
        }

        for (int ch = 0; ch < NCH; ++ch) {
            CP_WAIT(2);
            __syncthreads();
            if (ch + NSTG - 1 < NCH) {
                const int st = (ch + NSTG - 1) & (NSTG - 1);
                const int kb = (ch + NSTG - 1) * KS;
                cp16(sa0 + st * STGB, gA + kb);
                cp16(sa1 + st * STGB, gA + kb + 8);
                cp16(sb0 + st * STGB, gB + kb);
                cp16(sb1 + st * STGB, gB + kb + 8);
            }
            CP_COMMIT();

            const uint32_t soff = (uint32_t)((ch & (NSTG - 1)) * STGB);
#pragma unroll
            for (int kk = 0; kk < 2; ++kk) {
                const uint32_t x = kk ? 32u : 0u;
                uint32_t af[4][4], bf[2][4];
#pragma unroll
                for (int mi = 0; mi < 4; ++mi) LDSM4(af[mi], (aAddr[mi] + soff) ^ x);
#pragma unroll
                for (int p = 0; p < 2; ++p)    LDSM4(bf[p], (bAddr[p] + soff) ^ x);
#pragma unroll
                for (int mi = 0; mi < 4; ++mi)
#pragma unroll
                    for (int ni = 0; ni < 4; ++ni)
                        mma_bf16(acc[mi * 4 + ni], af[mi], &bf[ni >> 1][(ni & 1) * 2]);
            }
        }
        __syncthreads();
    }

    // Epilogue: raw preacts -> g_XWb (bf16 pairs)
    const int g = lane >> 2, q = lane & 3;
#pragma unroll
    for (int mi = 0; mi < 4; ++mi) {
        int m = mbase + m0 + mi * 16 + g;
        int t = m >> 8, b = m & 255;
        int dd = nbase >> 12;
        size_t rowbase = ((size_t)(dd * SEQ + t) * BATCH + b) * G4 + (nbase & 4095);
#pragma unroll
        for (int ni = 0; ni < 4; ++ni) {
            size_t off = rowbase + n0 + ni * 8 + 2 * q;
            __nv_bfloat162 v0, v1;
            v0.x = __float2bfloat16(acc[mi*4+ni][0]);
            v0.y = __float2bfloat16(acc[mi*4+ni][1]);
            v1.x = __float2bfloat16(acc[mi*4+ni][2]);
            v1.y = __float2bfloat16(acc[mi*4+ni][3]);
            *reinterpret_cast<__nv_bfloat162*>(g_XWb + off)          = v0;   // row b
            *reinterpret_cast<__nv_bfloat162*>(g_XWb + off + 8 * G4) = v1;   // row b+8
        }
    }
}

// ---------------------------------------------------------------------------
// Persistent recurrence: one launch, all 256 steps.
// Grid (64, 2): 64 N-tiles of 64 gate-cols x 2 dirs = 128 CTAs (1/SM).
// Wh resident in smem; h streamed per step (cp.async.cg); c in registers.
// Device barrier is PER-DIRECTION (64 CTAs each): dirs share no h state.
// ---------------------------------------------------------------------------
__global__ __launch_bounds__(256) void step_persist()
{
    extern __shared__ __align__(16) char sm[];
    const uint32_t smb = smem_u32(sm);
    const int tid = threadIdx.x;
    const int lane = tid & 31, warp = tid >> 5;
    const int d = blockIdx.y;
    const int nbase = blockIdx.x * 64;        // over G4
    const int m0 = (warp >> 1) * 64, n0 = (warp & 1) * 32;
    float* pre = reinterpret_cast<float*>(sm + SMP_PRE);
    float* biasSm = reinterpret_cast<float*>(sm + SMP_BIAS);
    const unsigned NDIR = gridDim.x;           // 64 CTAs per direction

    if (tid < 64) biasSm[tid] = g_biasI[(size_t)d * G4 + nbase + tid];

    // ---- Preload B (Wh) once: 32 chunks x (64 rows x 32 k), swizzled
    {
        const __nv_bfloat16* Bg = g_Whb + ((size_t)d * G4 + nbase) * HID;
#pragma unroll
        for (int v = 0; v < 32; ++v) {
            int j = v * 256 + tid;
            int ch = j >> 8, s2 = j & 255;
            int r = s2 >> 2, c = s2 & 3;
            cp16(smb + SMP_B + ch * 4096 + slotb(r, c),
                 Bg + (size_t)r * HID + ch * 32 + c * 8);
        }
        CP_COMMIT();
        CP_WAIT(0);
        __syncthreads();
    }

    // LDSM fragment addresses
    uint32_t aAddr[4], bAddr[2];
#pragma unroll
    for (int mi = 0; mi < 4; ++mi)
        aAddr[mi] = smb + SMP_A + slotb(m0 + mi * 16 + (lane & 15), lane >> 4);
#pragma unroll
    for (int p = 0; p < 2; ++p)
        bAddr[p] = smb + SMP_B
                 + slotb(n0 + (2 * p + ((lane >> 4) & 1)) * 8 + (lane & 7), (lane >> 3) & 1);

    // A-loader: thread covers rows rA+64v (v=0..3) at 16B-chunk cA
    const int rA = tid >> 2, cA = tid & 3;
    uint32_t aDst[4];
#pragma unroll
    for (int v = 0; v < 4; ++v)
        aDst[v] = smb + SMP_A + slotb((v << 6) + rA, cA);

    // Cell state in registers for the whole sequence (fixed thread mapping).
    float creg[2][8];
#pragma unroll
    for (int hh = 0; hh < 2; ++hh)
#pragma unroll
        for (int j = 0; j < 8; ++j) creg[hh][j] = 0.f;

    for (int s = 0; s < SEQ; ++s) {
        const int rb = s & 1, wb = rb ^ 1;
        const __nv_bfloat16* gA = g_hb + (size_t)rb * HB2 + (size_t)d * HB
                                       + (size_t)rA * HID + cA * 8;

        // Prologue: chunks 0,1 -> buffers 0,1
#pragma unroll
        for (int st = 0; st < 2; ++st) {
#pragma unroll
            for (int v = 0; v < 4; ++v)
                cp16cg(aDst[v] + st * 16384, gA + (size_t)(v << 6) * HID + st * KS);
            CP_COMMIT();
        }

        float acc[16][4];
#pragma unroll
        for (int i = 0; i < 16; ++i)
#pragma unroll
            for (int j = 0; j < 4; ++j) acc[i][j] = 0.f;

        int buf = 0, nxt = 2;
        for (int ch = 0; ch < NCH; ++ch) {
            CP_WAIT(1);
            __syncthreads();
            if (ch + 2 < NCH) {
#pragma unroll
                for (int v = 0; v < 4; ++v)
                    cp16cg(aDst[v] + nxt * 16384,
                           gA + (size_t)(v << 6) * HID + (ch + 2) * KS);
            }
            CP_COMMIT();

            const uint32_t aoff = (uint32_t)(buf * 16384);
            const uint32_t boff = (uint32_t)(ch * 4096);
#pragma unroll
            for (int kk = 0; kk < 2; ++kk) {
                const uint32_t x = kk ? 32u : 0u;
                uint32_t af[4][4], bf[2][4];
#pragma unroll
                for (int mi = 0; mi < 4; ++mi) LDSM4(af[mi], (aAddr[mi] + aoff) ^ x);
#pragma unroll
                for (int p = 0; p < 2; ++p)    LDSM4(bf[p], (bAddr[p] + boff) ^ x);
#pragma unroll
                for (int mi = 0; mi < 4; ++mi)
#pragma unroll
                    for (int ni = 0; ni < 4; ++ni)
                        mma_bf16(acc[mi * 4 + ni], af[mi], &bf[ni >> 1][(ni & 1) * 2]);
            }
            buf = (buf == 2) ? 0 : buf + 1;
            nxt = (nxt == 2) ? 0 : nxt + 1;
        }
        __syncthreads();

        // ---- Fused LSTM cell epilogue, two 128-row halves.
        // Prefetch this thread's XW: 32 bf16 (= 4 x uint4) PER HALF.
        const int tt = d ? (SEQ - 1 - s) : s;
        const int rr = tid & 127, hc = tid >> 7;
        uint4 xwr[2][4];
#pragma unroll
        for (int hh = 0; hh < 2; ++hh) {
            const __nv_bfloat16* xp = g_XWb
                + ((size_t)(d * SEQ + tt) * BATCH + (hh * 128 + rr)) * G4
                + nbase + hc * 32;
            xwr[hh][0] = *reinterpret_cast<const uint4*>(xp);
            xwr[hh][1] = *reinterpret_cast<const uint4*>(xp + 8);
            xwr[hh][2] = *reinterpret_cast<const uint4*>(xp + 16);
            xwr[hh][3] = *reinterpret_cast<const uint4*>(xp + 24);
        }

        const int g = lane >> 2, q = lane & 3;
#pragma unroll
        for (int hh = 0; hh < 2; ++hh) {
            if ((m0 < 128) == (hh == 0)) {
                const int rbase = m0 - hh * 128;
#pragma unroll
                for (int mi = 0; mi < 4; ++mi)
#pragma unroll
                    for (int half = 0; half < 2; ++half) {
                        int r = rbase + mi * 16 + g + half * 8;
#pragma unroll
                        for (int ni = 0; ni < 4; ++ni) {
                            int c = n0 + ni * 8 + 2 * q;
                            *reinterpret_cast<float2*>(&pre[r * PW + c]) =
                                make_float2(acc[mi*4+ni][half*2], acc[mi*4+ni][half*2+1]);
                        }
                    }
            }
            __syncthreads();
            {
                const int b = hh * 128 + rr;
                const float* prow = pre + rr * PW + hc * 32;
                __nv_bfloat16* hp = g_hb + (size_t)wb * HB2 + (size_t)d * HB
                                         + (size_t)b * HID + (nbase >> 2) + hc * 8;
                const __nv_bfloat16* xw16 = reinterpret_cast<const __nv_bfloat16*>(&xwr[hh][0]);
                uint32_t hbuf[4];
#pragma unroll
                for (int j = 0; j < 8; ++j) {
                    float4 pr = *reinterpret_cast<const float4*>(prow + 4 * j);
                    float4 bb = *reinterpret_cast<const float4*>(biasSm + hc * 32 + 4 * j);
                    float pi = pr.x + bb.x + __bfloat162float(xw16[4*j+0]);
                    float pf = pr.y + bb.y + __bfloat162float(xw16[4*j+1]);
                    float po = pr.z + bb.z + __bfloat162float(xw16[4*j+2]);
                    float pg = pr.w + bb.w + __bfloat162float(xw16[4*j+3]);
                    float ig = 1.f / (1.f + expf(-pi));
                    float fg = 1.f / (1.f + expf(-pf));
                    float og = 1.f / (1.f + expf(-po));
                    float gv = tanhf(pg);
                    float cc = fg * creg[hh][j] + ig * gv;
                    creg[hh][j] = cc;
                    float hv = og * tanhf(cc);
                    __nv_bfloat16 hb16 = __float2bfloat16(hv);
                    uint16_t raw = *reinterpret_cast<uint16_t*>(&hb16);
                    if (j & 1) hbuf[j >> 1] |= ((uint32_t)raw) << 16;
                    else       hbuf[j >> 1]  = raw;
                }
                *reinterpret_cast<uint4*>(hp) = *reinterpret_cast<uint4*>(hbuf);
            }
            __syncthreads();
        }

        // ---- Per-direction device barrier (64 CTAs; dirs are independent)
        if (tid == 0) {
            __threadfence();
            asm volatile("red.release.gpu.global.add.u32 [%0], 1;"
                         :: "l"(&g_bar2[d]) : "memory");
            const unsigned target = NDIR * (unsigned)(s + 1);
            unsigned v;
            do {
                asm volatile("ld.acquire.gpu.global.u32 %0, [%1];"
                             : "=r"(v) : "l"(&g_bar2[d]) : "memory");
            } while (v < target);
        }
        __syncthreads();
    }
}

// ---------------------------------------------------------------------------
__global__ void hsum_kernel()
{
    int i = blockIdx.x * blockDim.x + threadIdx.x;
    if (i < HB)
        g_hsum[i] = __bfloat162float(g_hb[i]) + __bfloat162float(g_hb[HB + i]);
}

// ---------------------------------------------------------------------------
// Output GEMM in fp32 FFMA (precision): M=256, N=32000, K=1024.
// ---------------------------------------------------------------------------
__global__ __launch_bounds__(256) void out_kernel(
    const float* __restrict__ Wout, const float* __restrict__ bout,
    float* __restrict__ out)
{
    __shared__ __align__(16) float As[2][8][128];
    __shared__ __align__(16) float Bs[2][8][128];

    const int tid   = threadIdx.x;
    const int nbase = blockIdx.x * 128;
    const int mbase = blockIdx.y * 128;

    const int a_m = tid >> 1, a_k = (tid & 1) * 4;
    const int b_n = tid >> 1, b_k = (tid & 1) * 4;
    const float* aptr = g_hsum + (size_t)(mbase + a_m) * HID;
    const float* bptr = Wout + (size_t)(nbase + b_n) * HID;

    float acc[8][8];
#pragma unroll
    for (int i = 0; i < 8; ++i)
#pragma unroll
        for (int j = 0; j < 8; ++j) acc[i][j] = 0.f;

    const int r0 = (tid >> 4) * 8;
    const int c0 = (tid & 15) * 8;

    float4 pa = *(const float4*)(aptr + a_k);
    float4 pb = *(const float4*)(bptr + b_k);
    As[0][a_k+0][a_m]=pa.x; As[0][a_k+1][a_m]=pa.y; As[0][a_k+2][a_m]=pa.z; As[0][a_k+3][a_m]=pa.w;
    Bs[0][b_k+0][b_n]=pb.x; Bs[0][b_k+1][b_n]=pb.y; Bs[0][b_k+2][b_n]=pb.z; Bs[0][b_k+3][b_n]=pb.w;
    __syncthreads();

    const int nit = HID / 8;
    for (int it = 0; it < nit; ++it) {
        int cur = it & 1;
        if (it + 1 < nit) {
            int k0 = (it + 1) * 8;
            pa = *(const float4*)(aptr + k0 + a_k);
            pb = *(const float4*)(bptr + k0 + b_k);
        }
#pragma unroll
        for (int kk = 0; kk < 8; ++kk) {
            float4 x0 = *(const float4*)&As[cur][kk][r0];
            float4 x1 = *(const float4*)&As[cur][kk][r0+4];
            float4 y0 = *(const float4*)&Bs[cur][kk][c0];
            float4 y1 = *(const float4*)&Bs[cur][kk][c0+4];
            float a[8] = {x0.x,x0.y,x0.z,x0.w,x1.x,x1.y,x1.z,x1.w};
            float b[8] = {y0.x,y0.y,y0.z,y0.w,y1.x,y1.y,y1.z,y1.w};
#pragma unroll
            for (int i = 0; i < 8; ++i)
#pragma unroll
                for (int j = 0; j < 8; ++j)
                    acc[i][j] = fmaf(a[i], b[j], acc[i][j]);
        }
        if (it + 1 < nit) {
            int nxt = cur ^ 1;
            As[nxt][a_k+0][a_m]=pa.x; As[nxt][a_k+1][a_m]=pa.y; As[nxt][a_k+2][a_m]=pa.z; As[nxt][a_k+3][a_m]=pa.w;
            Bs[nxt][b_k+0][b_n]=pb.x; Bs[nxt][b_k+1][b_n]=pb.y; Bs[nxt][b_k+2][b_n]=pb.z; Bs[nxt][b_k+3][b_n]=pb.w;
            __syncthreads();
        }
    }

#pragma unroll
    for (int i = 0; i < 8; ++i) {
        int m = mbase + r0 + i;
#pragma unroll
        for (int j = 0; j < 8; ++j) {
            int n = nbase + c0 + j;
            out[(size_t)m * NCLS + n] = acc[i][j] + bout[n];
        }
    }
}

// ---------------------------------------------------------------------------
extern "C" void kernel_launch(void* const* d_in, const int* in_sizes, int n_in,
                              void* d_out, int out_size)
{
    (void)in_sizes; (void)n_in; (void)out_size;
    const int*   X = (const int*)d_in[0];
    const float* C = (const float*)d_in[1];
    const float* W[8];
    const float* B[8];
    for (int i = 0; i < 8; ++i) W[i] = (const float*)d_in[2 + i];
    for (int i = 0; i < 8; ++i) B[i] = (const float*)d_in[10 + i];
    const float* Wout = (const float*)d_in[18];
    const float* bout = (const float*)d_in[19];
    float* out = (float*)d_out;

    static int smem_set = 0;
    if (!smem_set) {
        cudaFuncSetAttribute(xproj_hm, cudaFuncAttributeMaxDynamicSharedMemorySize, SMEMSZ);
        cudaFuncSetAttribute(step_persist, cudaFuncAttributeMaxDynamicSharedMemorySize, SMEMP);
        smem_set = 1;
    }

    init_kernel<<<(HB2 + 255) / 256, 256>>>();
    convw_kernel<<<16384, 256>>>(W[0],W[1],W[2],W[3],W[4],W[5],W[6],W[7]);
    convc_kernel<<<NCLS, 256>>>(C);
    bias_kernel<<<(2 * G4 + 255) / 256, 256>>>(B[0],B[1],B[2],B[3],B[4],B[5],B[6],B[7]);

    // Input projections (tensor cores, 2 CTAs/SM).
    xproj_hm<<<dim3(64, 512), 256, SMEMSZ>>>(X);

    // Entire recurrence: ONE persistent kernel, 128 co-resident CTAs.
    step_persist<<<dim3(64, 2), 256, SMEMP>>>();

    hsum_kernel<<<(HB + 255) / 256, 256>>>();
    out_kernel<<<dim3(NCLS / 128, BATCH / 128), 256>>>(Wout, bout, out);
}

// round 16
// speedup vs baseline: 1.2376x; 1.2376x over previous
#include <cuda_runtime.h>
#include <cuda_bf16.h>
#include <math.h>
#include <stdint.h>

#define BATCH 256
#define SEQ   256
#define EMB   1024
#define HID   1024
#define NCLS  32000
#define G4    4096          // 4 gates * HID
#define WROW  2048          // EMB + HID
#define HB    (BATCH*HID)   // 262144
#define HB2   (2*BATCH*HID) // 524288 (2 dirs)
#define KS    32            // K chunk
#define NCH   32            // 1024 / 32 chunks

// HMMA kernel smem layout (128x128 tile, 4-stage pipeline)
#define NSTG  4
#define STGB  8192          // 128 rows x 32 bf16 per stage
#define SMB_B 32768
#define SMEMSZ  69632

// persistent step kernel smem layout
#define PW       68                      // pre row stride (floats)
#define SMP_B    0                       // 32 x 4096 = 131072 (Wh resident)
#define SMP_A    131072                  // 3 x 16384 A buffers
#define SMP_PRE  (131072 + 49152)        // 128*68*4 = 34816
#define SMP_BIAS (131072 + 49152 + 34816)
#define SMEMP    (131072 + 49152 + 34816 + 256)   // 215296

// Scratch (device globals: allocation-free rule)
// VW[d][v][col*4+gi]: per-VOCAB x-preacts (dedup: depends only on token id)
static __device__ __nv_bfloat16  g_VW[(size_t)2 * NCLS * G4];   // 512 MB
static __device__ __nv_bfloat16  g_Cb[(size_t)NCLS * EMB];
static __device__ __nv_bfloat16  g_Whb[(size_t)2 * G4 * HID];   // [d][col*4+gi][k]
static __device__ __nv_bfloat16  g_Wxb[(size_t)2 * G4 * EMB];   // [d][col*4+gi][k]
static __device__ __nv_bfloat16  g_hb[2 * HB2];                 // [pingpong][dir][b][col]
static __device__ float          g_hsum[HB];                    // fp32 h1+h2
static __device__ float          g_biasI[2 * G4];
static __device__ unsigned       g_bar;                          // device-wide barrier

// ---------------------------------------------------------------------------
__device__ __forceinline__ uint32_t smem_u32(const void* p) {
    uint32_t a;
    asm("{ .reg .u64 t; cvta.to.shared.u64 t, %1; cvt.u32.u64 %0, t; }" : "=r"(a) : "l"(p));
    return a;
}
__device__ __forceinline__ void cp16(uint32_t s, const void* g) {
    asm volatile("cp.async.ca.shared.global [%0], [%1], 16;"
                 :: "r"(s), "l"(__cvta_generic_to_global(g)) : "memory");
}
__device__ __forceinline__ void cp16cg(uint32_t s, const void* g) {   // L1-bypass
    asm volatile("cp.async.cg.shared.global [%0], [%1], 16;"
                 :: "r"(s), "l"(__cvta_generic_to_global(g)) : "memory");
}
#define CP_COMMIT() asm volatile("cp.async.commit_group;" ::: "memory")
#define CP_WAIT(n)  asm volatile("cp.async.wait_group %0;" :: "n"(n) : "memory")

#define LDSM4(R, A) \
    asm volatile("ldmatrix.sync.aligned.m8n8.x4.shared.b16 {%0,%1,%2,%3}, [%4];" \
        : "=r"((R)[0]), "=r"((R)[1]), "=r"((R)[2]), "=r"((R)[3]) : "r"(A))

__device__ __forceinline__ void mma_bf16(float* d, const uint32_t* a, const uint32_t* b)
{
    asm volatile(
        "mma.sync.aligned.m16n8k16.row.col.f32.bf16.bf16.f32 "
        "{%0,%1,%2,%3}, {%4,%5,%6,%7}, {%8,%9}, {%0,%1,%2,%3};\n"
        : "+f"(d[0]), "+f"(d[1]), "+f"(d[2]), "+f"(d[3])
        : "r"(a[0]), "r"(a[1]), "r"(a[2]), "r"(a[3]), "r"(b[0]), "r"(b[1]));
}

// 16B-slot swizzle: row r, 16B-chunk c (0..3 over 32 bf16 k). Conflict-free.
__device__ __forceinline__ uint32_t slotb(int r, int c) {
    return (uint32_t)((r << 6) + ((c ^ ((r >> 1) & 3)) << 4));
}

// ---------------------------------------------------------------------------
__global__ void init_kernel()
{
    int i = blockIdx.x * blockDim.x + threadIdx.x;
    if (i == 0) g_bar = 0u;
    if (i < HB2) reinterpret_cast<uint32_t*>(g_hb)[i] = 0u;
}

__global__ __launch_bounds__(256) void convw_kernel(
    const float* __restrict__ W0, const float* __restrict__ W1,
    const float* __restrict__ W2, const float* __restrict__ W3,
    const float* __restrict__ W4, const float* __restrict__ W5,
    const float* __restrict__ W6, const float* __restrict__ W7)
{
    const float* Ws[8] = {W0,W1,W2,W3,W4,W5,W6,W7};
    int r = blockIdx.x;             // 0..16383
    int k = threadIdx.x * 4;
    const float* src;
    __nv_bfloat16* dst;
    if (r < 8192) {
        int d = r >> 12, np = r & 4095, gi = np & 3, col = np >> 2;
        src = Ws[d*4 + gi] + (size_t)col * WROW + EMB + k;
        dst = g_Whb + (size_t)r * HID + k;
    } else {
        int rr = r - 8192;
        int d = rr >> 12, np = rr & 4095, gi = np & 3, col = np >> 2;
        src = Ws[d*4 + gi] + (size_t)col * WROW + k;
        dst = g_Wxb + (size_t)rr * EMB + k;
    }
    float4 v = *(const float4*)src;
    __nv_bfloat162 lo; lo.x = __float2bfloat16(v.x); lo.y = __float2bfloat16(v.y);
    __nv_bfloat162 hi; hi.x = __float2bfloat16(v.z); hi.y = __float2bfloat16(v.w);
    *reinterpret_cast<__nv_bfloat162*>(dst)     = lo;
    *reinterpret_cast<__nv_bfloat162*>(dst + 2) = hi;
}

__global__ __launch_bounds__(256) void convc_kernel(const float* __restrict__ C)
{
    size_t row = blockIdx.x;
    int k = threadIdx.x * 4;
    float4 v = *(const float4*)(C + row * EMB + k);
    __nv_bfloat16* dst = g_Cb + row * EMB + k;
    __nv_bfloat162 lo; lo.x = __float2bfloat16(v.x); lo.y = __float2bfloat16(v.y);
    __nv_bfloat162 hi; hi.x = __float2bfloat16(v.z); hi.y = __float2bfloat16(v.w);
    *reinterpret_cast<__nv_bfloat162*>(dst)     = lo;
    *reinterpret_cast<__nv_bfloat162*>(dst + 2) = hi;
}

__global__ void bias_kernel(
    const float* __restrict__ B0, const float* __restrict__ B1,
    const float* __restrict__ B2, const float* __restrict__ B3,
    const float* __restrict__ B4, const float* __restrict__ B5,
    const float* __restrict__ B6, const float* __restrict__ B7)
{
    const float* Bs[8] = {B0,B1,B2,B3,B4,B5,B6,B7};
    int n = blockIdx.x * blockDim.x + threadIdx.x;
    if (n < 2 * G4) {
        int d = n >> 12, rr = n & 4095, gi = rr & 3, col = rr >> 2;
        g_biasI[n] = Bs[d*4 + gi][col];
    }
}

// ---------------------------------------------------------------------------
// vproj: VW[v] = C[v] @ Wx^T for ALL vocab rows (token-dedup of xproj:
// 0.49x the FLOPs of the per-(t,b) projection; result depends only on v).
// 128x128 tile, 8 warps (2m x 4n), KS=32, 4-stage cp.async, ldmatrix.
// ---------------------------------------------------------------------------
__global__ __launch_bounds__(256) void vproj_hm()
{
    extern __shared__ __align__(16) char sm[];
    const uint32_t smb = smem_u32(sm);
    const int tid = threadIdx.x;
    const int lane = tid & 31, warp = tid >> 5;
    const int nbase = blockIdx.x * 128;   // over 8192
    const int mbase = blockIdx.y * 128;   // over 32000 (250 tiles)
    const int m0 = (warp >> 2) * 64, n0 = (warp & 3) * 32;

    const __nv_bfloat16* aRow = g_Cb + (size_t)(mbase + (tid >> 1)) * EMB;
    const __nv_bfloat16* bRow = g_Wxb + (size_t)(nbase + (tid >> 1)) * EMB;

    float acc[16][4];
#pragma unroll
    for (int i = 0; i < 16; ++i)
#pragma unroll
        for (int j = 0; j < 4; ++j) acc[i][j] = 0.f;

    {
        const int rL = tid >> 1, cL = (tid & 1) * 2;
        const uint32_t sa0 = smb + slotb(rL, cL);
        const uint32_t sa1 = smb + slotb(rL, cL + 1);
        const uint32_t sb0 = smb + SMB_B + slotb(rL, cL);
        const uint32_t sb1 = smb + SMB_B + slotb(rL, cL + 1);
        const __nv_bfloat16* gA = aRow + cL * 8;
        const __nv_bfloat16* gB = bRow + cL * 8;

        uint32_t aAddr[4], bAddr[2];
#pragma unroll
        for (int mi = 0; mi < 4; ++mi)
            aAddr[mi] = smb + slotb(m0 + mi * 16 + (lane & 15), lane >> 4);
#pragma unroll
        for (int p = 0; p < 2; ++p)
            bAddr[p] = smb + SMB_B
                     + slotb(n0 + (2 * p + ((lane >> 4) & 1)) * 8 + (lane & 7), (lane >> 3) & 1);

#pragma unroll
        for (int st = 0; st < NSTG - 1; ++st) {
            const int kb = st * KS;
            cp16(sa0 + st * STGB, gA + kb);
            cp16(sa1 + st * STGB, gA + kb + 8);
            cp16(sb0 + st * STGB, gB + kb);
            cp16(sb1 + st * STGB, gB + kb + 8);
            CP_COMMIT();
        }

        for (int ch = 0; ch < NCH; ++ch) {
            CP_WAIT(2);
            __syncthreads();
            if (ch + NSTG - 1 < NCH) {
                const int st = (ch + NSTG - 1) & (NSTG - 1);
                const int kb = (ch + NSTG - 1) * KS;
                cp16(sa0 + st * STGB, gA + kb);
                cp16(sa1 + st * STGB, gA + kb + 8);
                cp16(sb0 + st * STGB, gB + kb);
                cp16(sb1 + st * STGB, gB + kb + 8);
            }
            CP_COMMIT();

            const uint32_t soff = (uint32_t)((ch & (NSTG - 1)) * STGB);
#pragma unroll
            for (int kk = 0; kk < 2; ++kk) {
                const uint32_t x = kk ? 32u : 0u;
                uint32_t af[4][4], bf[2][4];
#pragma unroll
                for (int mi = 0; mi < 4; ++mi) LDSM4(af[mi], (aAddr[mi] + soff) ^ x);
#pragma unroll
                for (int p = 0; p < 2; ++p)    LDSM4(bf[p], (bAddr[p] + soff) ^ x);
#pragma unroll
                for (int mi = 0; mi < 4; ++mi)
#pragma unroll
                    for (int ni = 0; ni < 4; ++ni)
                        mma_bf16(acc[mi * 4 + ni], af[mi], &bf[ni >> 1][(ni & 1) * 2]);
            }
        }
        __syncthreads();
    }

    // Epilogue: raw preacts -> g_VW[d][v][rr] (bf16 pairs)
    const int g = lane >> 2, q = lane & 3;
#pragma unroll
    for (int mi = 0; mi < 4; ++mi) {
        int v = mbase + m0 + mi * 16 + g;
        int dd = nbase >> 12;
        size_t rowbase = ((size_t)dd * NCLS + v) * G4 + (nbase & 4095);
#pragma unroll
        for (int ni = 0; ni < 4; ++ni) {
            size_t off = rowbase + n0 + ni * 8 + 2 * q;
            __nv_bfloat162 v0, v1;
            v0.x = __float2bfloat16(acc[mi*4+ni][0]);
            v0.y = __float2bfloat16(acc[mi*4+ni][1]);
            v1.x = __float2bfloat16(acc[mi*4+ni][2]);
            v1.y = __float2bfloat16(acc[mi*4+ni][3]);
            *reinterpret_cast<__nv_bfloat162*>(g_VW + off)          = v0;   // row v
            *reinterpret_cast<__nv_bfloat162*>(g_VW + off + 8 * G4) = v1;   // row v+8
        }
    }
}

// ---------------------------------------------------------------------------
// Persistent recurrence: one launch, all 256 steps.
// Grid (64, 2): 64 N-tiles of 64 gate-cols x 2 dirs = 128 CTAs (1/SM).
// Wh resident in smem; h streamed per step (cp.async.cg); c in registers.
// x-preacts gathered from the vocab table g_VW[d][X[b][t]].
// ---------------------------------------------------------------------------
__global__ __launch_bounds__(256) void step_persist(const int* __restrict__ X)
{
    extern __shared__ __align__(16) char sm[];
    const uint32_t smb = smem_u32(sm);
    const int tid = threadIdx.x;
    const int lane = tid & 31, warp = tid >> 5;
    const int d = blockIdx.y;
    const int nbase = blockIdx.x * 64;        // over G4
    const int m0 = (warp >> 1) * 64, n0 = (warp & 1) * 32;
    float* pre = reinterpret_cast<float*>(sm + SMP_PRE);
    float* biasSm = reinterpret_cast<float*>(sm + SMP_BIAS);
    const unsigned NCTA = gridDim.x * gridDim.y;

    if (tid < 64) biasSm[tid] = g_biasI[(size_t)d * G4 + nbase + tid];

    // ---- Preload B (Wh) once: 32 chunks x (64 rows x 32 k), swizzled
    {
        const __nv_bfloat16* Bg = g_Whb + ((size_t)d * G4 + nbase) * HID;
#pragma unroll
        for (int v = 0; v < 32; ++v) {
            int j = v * 256 + tid;
            int ch = j >> 8, s2 = j & 255;
            int r = s2 >> 2, c = s2 & 3;
            cp16(smb + SMP_B + ch * 4096 + slotb(r, c),
                 Bg + (size_t)r * HID + ch * 32 + c * 8);
        }
        CP_COMMIT();
        CP_WAIT(0);
        __syncthreads();
    }

    // LDSM fragment addresses
    uint32_t aAddr[4], bAddr[2];
#pragma unroll
    for (int mi = 0; mi < 4; ++mi)
        aAddr[mi] = smb + SMP_A + slotb(m0 + mi * 16 + (lane & 15), lane >> 4);
#pragma unroll
    for (int p = 0; p < 2; ++p)
        bAddr[p] = smb + SMP_B
                 + slotb(n0 + (2 * p + ((lane >> 4) & 1)) * 8 + (lane & 7), (lane >> 3) & 1);

    // A-loader: thread covers rows rA+64v (v=0..3) at 16B-chunk cA
    const int rA = tid >> 2, cA = tid & 3;
    uint32_t aDst[4];
#pragma unroll
    for (int v = 0; v < 4; ++v)
        aDst[v] = smb + SMP_A + slotb((v << 6) + rA, cA);

    // Cell state in registers for the whole sequence (fixed thread mapping).
    float creg[2][8];
#pragma unroll
    for (int hh = 0; hh < 2; ++hh)
#pragma unroll
        for (int j = 0; j < 8; ++j) creg[hh][j] = 0.f;

    for (int s = 0; s < SEQ; ++s) {
        const int rb = s & 1, wb = rb ^ 1;
        const __nv_bfloat16* gA = g_hb + (size_t)rb * HB2 + (size_t)d * HB
                                       + (size_t)rA * HID + cA * 8;

        // Prologue: chunks 0,1 -> buffers 0,1
#pragma unroll
        for (int st = 0; st < 2; ++st) {
#pragma unroll
            for (int v = 0; v < 4; ++v)
                cp16cg(aDst[v] + st * 16384, gA + (size_t)(v << 6) * HID + st * KS);
            CP_COMMIT();
        }

        float acc[16][4];
#pragma unroll
        for (int i = 0; i < 16; ++i)
#pragma unroll
            for (int j = 0; j < 4; ++j) acc[i][j] = 0.f;

        int buf = 0, nxt = 2;
        for (int ch = 0; ch < NCH; ++ch) {
            CP_WAIT(1);
            __syncthreads();
            if (ch + 2 < NCH) {
#pragma unroll
                for (int v = 0; v < 4; ++v)
                    cp16cg(aDst[v] + nxt * 16384,
                           gA + (size_t)(v << 6) * HID + (ch + 2) * KS);
            }
            CP_COMMIT();

            const uint32_t aoff = (uint32_t)(buf * 16384);
            const uint32_t boff = (uint32_t)(ch * 4096);
#pragma unroll
            for (int kk = 0; kk < 2; ++kk) {
                const uint32_t x = kk ? 32u : 0u;
                uint32_t af[4][4], bf[2][4];
#pragma unroll
                for (int mi = 0; mi < 4; ++mi) LDSM4(af[mi], (aAddr[mi] + aoff) ^ x);
#pragma unroll
                for (int p = 0; p < 2; ++p)    LDSM4(bf[p], (bAddr[p] + boff) ^ x);
#pragma unroll
                for (int mi = 0; mi < 4; ++mi)
#pragma unroll
                    for (int ni = 0; ni < 4; ++ni)
                        mma_bf16(acc[mi * 4 + ni], af[mi], &bf[ni >> 1][(ni & 1) * 2]);
            }
            buf = (buf == 2) ? 0 : buf + 1;
            nxt = (nxt == 2) ? 0 : nxt + 1;
        }
        __syncthreads();

        // ---- Fused LSTM cell epilogue, two 128-row halves.
        // Gather this thread's x-preacts from VW[d][tok]: 32 bf16 PER HALF.
        const int tt = d ? (SEQ - 1 - s) : s;
        const int rr = tid & 127, hc = tid >> 7;
        const int tok0 = X[(size_t)rr * SEQ + tt];           // batch row rr
        const int tok1 = X[(size_t)(128 + rr) * SEQ + tt];   // batch row 128+rr
        uint4 xwr[2][4];
        {
            const __nv_bfloat16* xp0 = g_VW + ((size_t)d * NCLS + tok0) * G4
                                            + nbase + hc * 32;
            const __nv_bfloat16* xp1 = g_VW + ((size_t)d * NCLS + tok1) * G4
                                            + nbase + hc * 32;
            xwr[0][0] = *reinterpret_cast<const uint4*>(xp0);
            xwr[0][1] = *reinterpret_cast<const uint4*>(xp0 + 8);
            xwr[0][2] = *reinterpret_cast<const uint4*>(xp0 + 16);
            xwr[0][3] = *reinterpret_cast<const uint4*>(xp0 + 24);
            xwr[1][0] = *reinterpret_cast<const uint4*>(xp1);
            xwr[1][1] = *reinterpret_cast<const uint4*>(xp1 + 8);
            xwr[1][2] = *reinterpret_cast<const uint4*>(xp1 + 16);
            xwr[1][3] = *reinterpret_cast<const uint4*>(xp1 + 24);
        }

        const int g = lane >> 2, q = lane & 3;
#pragma unroll
        for (int hh = 0; hh < 2; ++hh) {
            if ((m0 < 128) == (hh == 0)) {
                const int rbase = m0 - hh * 128;
#pragma unroll
                for (int mi = 0; mi < 4; ++mi)
#pragma unroll
                    for (int half = 0; half < 2; ++half) {
                        int r = rbase + mi * 16 + g + half * 8;
#pragma unroll
                        for (int ni = 0; ni < 4; ++ni) {
                            int c = n0 + ni * 8 + 2 * q;
                            *reinterpret_cast<float2*>(&pre[r * PW + c]) =
                                make_float2(acc[mi*4+ni][half*2], acc[mi*4+ni][half*2+1]);
                        }
                    }
            }
            __syncthreads();
            {
                const int b = hh * 128 + rr;
                const float* prow = pre + rr * PW + hc * 32;
                __nv_bfloat16* hp = g_hb + (size_t)wb * HB2 + (size_t)d * HB
                                         + (size_t)b * HID + (nbase >> 2) + hc * 8;
                const __nv_bfloat16* xw16 = reinterpret_cast<const __nv_bfloat16*>(&xwr[hh][0]);
                uint32_t hbuf[4];
#pragma unroll
                for (int j = 0; j < 8; ++j) {
                    float4 pr = *reinterpret_cast<const float4*>(prow + 4 * j);
                    float4 bb = *reinterpret_cast<const float4*>(biasSm + hc * 32 + 4 * j);
                    float pi = pr.x + bb.x + __bfloat162float(xw16[4*j+0]);
                    float pf = pr.y + bb.y + __bfloat162float(xw16[4*j+1]);
                    float po = pr.z + bb.z + __bfloat162float(xw16[4*j+2]);
                    float pg = pr.w + bb.w + __bfloat162float(xw16[4*j+3]);
                    float ig = 1.f / (1.f + expf(-pi));
                    float fg = 1.f / (1.f + expf(-pf));
                    float og = 1.f / (1.f + expf(-po));
                    float gv = tanhf(pg);
                    float cc = fg * creg[hh][j] + ig * gv;
                    creg[hh][j] = cc;
                    float hv = og * tanhf(cc);
                    __nv_bfloat16 hb16 = __float2bfloat16(hv);
                    uint16_t raw = *reinterpret_cast<uint16_t*>(&hb16);
                    if (j & 1) hbuf[j >> 1] |= ((uint32_t)raw) << 16;
                    else       hbuf[j >> 1]  = raw;
                }
                *reinterpret_cast<uint4*>(hp) = *reinterpret_cast<uint4*>(hbuf);
            }
            __syncthreads();
        }

        // ---- Device-wide barrier
        if (tid == 0) {
            __threadfence();
            asm volatile("red.release.gpu.global.add.u32 [%0], 1;"
                         :: "l"(&g_bar) : "memory");
            const unsigned target = NCTA * (unsigned)(s + 1);
            unsigned v;
            do {
                asm volatile("ld.acquire.gpu.global.u32 %0, [%1];"
                             : "=r"(v) : "l"(&g_bar) : "memory");
            } while (v < target);
        }
        __syncthreads();
    }
}

// ---------------------------------------------------------------------------
__global__ void hsum_kernel()
{
    int i = blockIdx.x * blockDim.x + threadIdx.x;
    if (i < HB)
        g_hsum[i] = __bfloat162float(g_hb[i]) + __bfloat162float(g_hb[HB + i]);
}

// ---------------------------------------------------------------------------
// Output GEMM in fp32 FFMA (precision): M=256, N=32000, K=1024.
// ---------------------------------------------------------------------------
__global__ __launch_bounds__(256) void out_kernel(
    const float* __restrict__ Wout, const float* __restrict__ bout,
    float* __restrict__ out)
{
    __shared__ __align__(16) float As[2][8][128];
    __shared__ __align__(16) float Bs[2][8][128];

    const int tid   = threadIdx.x;
    const int nbase = blockIdx.x * 128;
    const int mbase = blockIdx.y * 128;

    const int a_m = tid >> 1, a_k = (tid & 1) * 4;
    const int b_n = tid >> 1, b_k = (tid & 1) * 4;
    const float* aptr = g_hsum + (size_t)(mbase + a_m) * HID;
    const float* bptr = Wout + (size_t)(nbase + b_n) * HID;

    float acc[8][8];
#pragma unroll
    for (int i = 0; i < 8; ++i)
#pragma unroll
        for (int j = 0; j < 8; ++j) acc[i][j] = 0.f;

    const int r0 = (tid >> 4) * 8;
    const int c0 = (tid & 15) * 8;

    float4 pa = *(const float4*)(aptr + a_k);
    float4 pb = *(const float4*)(bptr + b_k);
    As[0][a_k+0][a_m]=pa.x; As[0][a_k+1][a_m]=pa.y; As[0][a_k+2][a_m]=pa.z; As[0][a_k+3][a_m]=pa.w;
    Bs[0][b_k+0][b_n]=pb.x; Bs[0][b_k+1][b_n]=pb.y; Bs[0][b_k+2][b_n]=pb.z; Bs[0][b_k+3][b_n]=pb.w;
    __syncthreads();

    const int nit = HID / 8;
    for (int it = 0; it < nit; ++it) {
        int cur = it & 1;
        if (it + 1 < nit) {
            int k0 = (it + 1) * 8;
            pa = *(const float4*)(aptr + k0 + a_k);
            pb = *(const float4*)(bptr + k0 + b_k);
        }
#pragma unroll
        for (int kk = 0; kk < 8; ++kk) {
            float4 x0 = *(const float4*)&As[cur][kk][r0];
            float4 x1 = *(const float4*)&As[cur][kk][r0+4];
            float4 y0 = *(const float4*)&Bs[cur][kk][c0];
            float4 y1 = *(const float4*)&Bs[cur][kk][c0+4];
            float a[8] = {x0.x,x0.y,x0.z,x0.w,x1.x,x1.y,x1.z,x1.w};
            float b[8] = {y0.x,y0.y,y0.z,y0.w,y1.x,y1.y,y1.z,y1.w};
#pragma unroll
            for (int i = 0; i < 8; ++i)
#pragma unroll
                for (int j = 0; j < 8; ++j)
                    acc[i][j] = fmaf(a[i], b[j], acc[i][j]);
        }
        if (it + 1 < nit) {
            int nxt = cur ^ 1;
            As[nxt][a_k+0][a_m]=pa.x; As[nxt][a_k+1][a_m]=pa.y; As[nxt][a_k+2][a_m]=pa.z; As[nxt][a_k+3][a_m]=pa.w;
            Bs[nxt][b_k+0][b_n]=pb.x; Bs[nxt][b_k+1][b_n]=pb.y; Bs[nxt][b_k+2][b_n]=pb.z; Bs[nxt][b_k+3][b_n]=pb.w;
            __syncthreads();
        }
    }

#pragma unroll
    for (int i = 0; i < 8; ++i) {
        int m = mbase + r0 + i;
#pragma unroll
        for (int j = 0; j < 8; ++j) {
            int n = nbase + c0 + j;
            out[(size_t)m * NCLS + n] = acc[i][j] + bout[n];
        }
    }
}

// ---------------------------------------------------------------------------
extern "C" void kernel_launch(void* const* d_in, const int* in_sizes, int n_in,
                              void* d_out, int out_size)
{
    (void)in_sizes; (void)n_in; (void)out_size;
    const int*   X = (const int*)d_in[0];
    const float* C = (const float*)d_in[1];
    const float* W[8];
    const float* B[8];
    for (int i = 0; i < 8; ++i) W[i] = (const float*)d_in[2 + i];
    for (int i = 0; i < 8; ++i) B[i] = (const float*)d_in[10 + i];
    const float* Wout = (const float*)d_in[18];
    const float* bout = (const float*)d_in[19];
    float* out = (float*)d_out;

    static int smem_set = 0;
    if (!smem_set) {
        cudaFuncSetAttribute(vproj_hm, cudaFuncAttributeMaxDynamicSharedMemorySize, SMEMSZ);
        cudaFuncSetAttribute(step_persist, cudaFuncAttributeMaxDynamicSharedMemorySize, SMEMP);
        smem_set = 1;
    }

    init_kernel<<<(HB2 + 255) / 256, 256>>>();
    convw_kernel<<<16384, 256>>>(W[0],W[1],W[2],W[3],W[4],W[5],W[6],W[7]);
    convc_kernel<<<NCLS, 256>>>(C);
    bias_kernel<<<(2 * G4 + 255) / 256, 256>>>(B[0],B[1],B[2],B[3],B[4],B[5],B[6],B[7]);

    // Per-VOCAB input projection (token dedup: 0.49x FLOPs of per-(t,b)).
    vproj_hm<<<dim3(64, NCLS / 128), 256, SMEMSZ>>>();

    // Entire recurrence: ONE persistent kernel, 128 co-resident CTAs.
    step_persist<<<dim3(64, 2), 256, SMEMP>>>(X);

    hsum_kernel<<<(HB + 255) / 256, 256>>>();
    out_kernel<<<dim3(NCLS / 128, BATCH / 128), 256>>>(Wout, bout, out);
}